// round 15
// baseline (speedup 1.0000x reference)
#include <cuda_runtime.h>
#include <cuda_fp16.h>
#include <cstdint>

// ---------------------------------------------------------------------------
// Problem constants
// ---------------------------------------------------------------------------
#define TOKENS  16384
#define DIN     1024
#define DOUT    1024
#define NEXP    8
#define TOPK    2
#define NSLOTS  (TOKENS * TOPK)   // 32768

// GEMM tiling (mma.sync m16n8k16 fp16, f16 chain accum -> fp32 promote per kc)
#define BM 128
#define BN 128
#define BK 64
#define NK (DIN / BK)             // 16 k-chunks
#define NSTAGE 4

// smem: per stage 2 tiles (A, B), each 128 rows x 128B (64 fp16)
#define TILE_B   (128 * 128)      // 16384
#define ST_A     0
#define ST_B     (TILE_B)
#define STAGE_B  (2 * TILE_B)     // 32768
#define SMEM_TOTAL (NSTAGE * STAGE_B)   // 131072

// ---------------------------------------------------------------------------
// Device scratch (no cudaMalloc allowed)
// ---------------------------------------------------------------------------
__device__ int g_row[NSLOTS];
__device__ int g_off[NEXP + 1];
__device__ __half g_xh[TOKENS * DIN];            // 32MB fp16 inputs
__device__ __half g_wh[NEXP * DOUT * DIN];       // 16MB fp16 weights
__device__ __half g_slot[(size_t)NSLOTS * DOUT]; // 64MB gate-scaled slot outputs (fp16)

// ---------------------------------------------------------------------------
// Helpers
// ---------------------------------------------------------------------------
__device__ __forceinline__ uint32_t smem_u32(const void* p) {
    uint32_t a;
    asm("{ .reg .u64 t; cvta.to.shared.u64 t, %1; cvt.u32.u64 %0, t; }" : "=r"(a) : "l"(p));
    return a;
}
__device__ __forceinline__ uint32_t swz128(uint32_t o) { return o ^ ((o >> 3) & 0x70); }

__device__ __forceinline__ void cpa16(uint32_t dst, const void* src) {
    asm volatile("cp.async.cg.shared.global [%0], [%1], 16;" :: "r"(dst), "l"(src) : "memory");
}
#define CPA_COMMIT() asm volatile("cp.async.commit_group;" ::: "memory")
#define CPA_WAIT(n)  asm volatile("cp.async.wait_group %0;" :: "n"(n) : "memory")

__device__ __forceinline__ void ldsm_x4(uint32_t* r, uint32_t addr) {
    asm volatile("ldmatrix.sync.aligned.m8n8.x4.shared.b16 {%0,%1,%2,%3}, [%4];"
                 : "=r"(r[0]), "=r"(r[1]), "=r"(r[2]), "=r"(r[3]) : "r"(addr));
}

// f16-accumulate mma: D(f16x2 x2) = A*B + C(f16x2 x2)
__device__ __forceinline__ void mma_h(uint32_t* d, const uint32_t* a, const uint32_t* b,
                                      const uint32_t* c) {
    asm volatile(
        "mma.sync.aligned.m16n8k16.row.col.f16.f16.f16.f16 "
        "{%0,%1}, {%2,%3,%4,%5}, {%6,%7}, {%8,%9};"
        : "=r"(d[0]), "=r"(d[1])
        : "r"(a[0]), "r"(a[1]), "r"(a[2]), "r"(a[3]), "r"(b[0]), "r"(b[1]),
          "r"(c[0]), "r"(c[1]));
}

// ---------------------------------------------------------------------------
// Index normalization (int32/int64 auto-detect; validated in R3)
// ---------------------------------------------------------------------------
__global__ void normalize_kernel(const void* __restrict__ scat,
                                 const void* __restrict__ offs) {
    const unsigned* ow = (const unsigned*)offs;
    const bool is64 = (ow[1] == 0u);
    int gid = blockIdx.x * blockDim.x + threadIdx.x;
    int stride = gridDim.x * blockDim.x;
    if (gid == 0) g_off[0] = 0;
    if (gid >= 1 && gid <= NEXP) {
        g_off[gid] = is64 ? (int)((const long long*)offs)[gid - 1]
                          : ((const int*)offs)[gid - 1];
    }
    for (int s = gid; s < NSLOTS; s += stride) {
        long long v = is64 ? ((const long long*)scat)[s]
                           : (long long)((const int*)scat)[s];
        g_row[s] = (int)(v / TOPK);
    }
}

// ---------------------------------------------------------------------------
// fp32 -> fp16 conversion for x and W
// ---------------------------------------------------------------------------
__global__ void convert_kernel(const float* __restrict__ x,
                               const float* __restrict__ w) {
    int gid = blockIdx.x * blockDim.x + threadIdx.x;
    int stride = gridDim.x * blockDim.x;
    const int NX4 = TOKENS * DIN / 4;
    const int NW4 = NEXP * DOUT * DIN / 4;
    const float4* x4 = (const float4*)x;
    const float4* w4 = (const float4*)w;
    __half2* xh = (__half2*)g_xh;
    __half2* wh = (__half2*)g_wh;
    for (int i = gid; i < NX4; i += stride) {
        float4 v = x4[i];
        xh[2 * i + 0] = __floats2half2_rn(v.x, v.y);
        xh[2 * i + 1] = __floats2half2_rn(v.z, v.w);
    }
    for (int i = gid; i < NW4; i += stride) {
        float4 v = w4[i];
        wh[2 * i + 0] = __floats2half2_rn(v.x, v.y);
        wh[2 * i + 1] = __floats2half2_rn(v.z, v.w);
    }
}

// ---------------------------------------------------------------------------
// mma.sync fp16 grouped GEMM, 4-stage cp.async pipeline.
// f16 accumulator chain within each 64-wide K chunk (4 mma), promoted to fp32
// registers once per chunk: bounds fp16 accumulation error to ~5e-4 while
// running the tensor pipe at f16-accumulate rate.
// grid: x = n-tile (8), y = m-tile within expert (256), z = expert (8)
// 256 threads = 8 warps in 4(m) x 2(n); warp tile 32x64.
// Epilogue: gate-scaled fp16 STG to g_slot (combine kernel sums slot pairs).
// ---------------------------------------------------------------------------
__global__ __launch_bounds__(256, 1)
void moe_mma_kernel(const float* __restrict__ gates) {
    const int e    = blockIdx.z;
    const int off0 = g_off[e];
    const int off1 = g_off[e + 1];
    const int m0   = off0 + blockIdx.y * BM;
    if (m0 >= off1) return;
    const int n0   = blockIdx.x * BN;

    extern __shared__ char smem[];
    const uint32_t sb = smem_u32(smem);
    const int tid  = threadIdx.x;
    const int lane = tid & 31;
    const int wid  = tid >> 5;
    const int wm   = wid & 3;         // m-warp 0..3
    const int wn   = wid >> 2;        // n-warp 0..1

    // ---------------- loader setup: thread -> (row, half-row) --------------
    const int lr = tid >> 1;          // row 0..127 (both A and B tiles)
    const int lh = tid & 1;           // which half of the 128B row
    int sclamp = m0 + lr;
    if (sclamp >= off1) sclamp = off1 - 1;
    const int rowA = g_row[sclamp];
    const __half* pA = g_xh + (size_t)rowA * DIN;
    const __half* pB = g_wh + ((size_t)e << 20) + (size_t)(n0 + lr) * DIN;
    uint32_t so[4];                   // swizzled dst offsets within a tile
#pragma unroll
    for (int j = 0; j < 4; j++)
        so[j] = swz128((uint32_t)lr * 128 + (uint32_t)(lh * 4 + j) * 16);

    // fp32 accumulators: [mt][nt][4]
    float acc[2][8][4];
#pragma unroll
    for (int mt = 0; mt < 2; mt++)
#pragma unroll
        for (int nt = 0; nt < 8; nt++)
#pragma unroll
            for (int q = 0; q < 4; q++) acc[mt][nt][q] = 0.f;

    // ---------------- prefetch stages 0..NSTAGE-2 ----------------
#pragma unroll
    for (int ps = 0; ps < NSTAGE - 1; ps++) {
        const uint32_t base = sb + ps * STAGE_B;
        const int k0 = ps * BK;
#pragma unroll
        for (int j = 0; j < 4; j++) {
            const int eo = k0 + (lh * 4 + j) * 8;
            cpa16(base + ST_A + so[j], pA + eo);
            cpa16(base + ST_B + so[j], pB + eo);
        }
        CPA_COMMIT();
    }

    // ldmatrix address lane maps (validated in R10/R13)
    const int a_r = lane & 15, a_c = lane >> 4;                        // A x4
    const int b_r = lane & 7, b_k = (lane >> 3) & 1, b_n = lane >> 4;  // B x4

    // ---------------- main loop ----------------
    for (int kc = 0; kc < NK; kc++) {
        CPA_WAIT(NSTAGE - 2);
        __syncthreads();

        // issue loads for chunk kc+NSTAGE-1
        const int nk = kc + NSTAGE - 1;
        if (nk < NK) {
            const uint32_t base = sb + (nk % NSTAGE) * STAGE_B;
            const int k0 = nk * BK;
#pragma unroll
            for (int j = 0; j < 4; j++) {
                const int eo = k0 + (lh * 4 + j) * 8;
                cpa16(base + ST_A + so[j], pA + eo);
                cpa16(base + ST_B + so[j], pB + eo);
            }
        }
        CPA_COMMIT();

        // compute on stage kc%NSTAGE — f16 accumulator chain over 4 k16 steps
        const uint32_t base = sb + (kc % NSTAGE) * STAGE_B;
        uint32_t d16[2][8][2];
#pragma unroll
        for (int ks = 0; ks < 4; ks++) {
            uint32_t af[2][4];
#pragma unroll
            for (int mt = 0; mt < 2; mt++) {
                const uint32_t off =
                    swz128((uint32_t)(wm * 32 + mt * 16 + a_r) * 128 +
                           (uint32_t)(ks * 32 + a_c * 16));
                ldsm_x4(af[mt], base + ST_A + off);
            }
            uint32_t bf[4][4];
#pragma unroll
            for (int g = 0; g < 4; g++) {
                const uint32_t off =
                    swz128((uint32_t)(wn * 64 + g * 16 + b_n * 8 + b_r) * 128 +
                           (uint32_t)(ks * 32 + b_k * 16));
                ldsm_x4(bf[g], base + ST_B + off);
            }
            const uint32_t zz[2] = {0u, 0u};
#pragma unroll
            for (int mt = 0; mt < 2; mt++) {
#pragma unroll
                for (int g = 0; g < 4; g++) {
                    if (ks == 0) {
                        mma_h(d16[mt][2 * g],     af[mt], &bf[g][0], zz);
                        mma_h(d16[mt][2 * g + 1], af[mt], &bf[g][2], zz);
                    } else {
                        mma_h(d16[mt][2 * g],     af[mt], &bf[g][0], d16[mt][2 * g]);
                        mma_h(d16[mt][2 * g + 1], af[mt], &bf[g][2], d16[mt][2 * g + 1]);
                    }
                }
            }
        }
        // promote f16 chunk sums to fp32 accumulators (fma pipe, overlaps)
#pragma unroll
        for (int mt = 0; mt < 2; mt++) {
#pragma unroll
            for (int nt = 0; nt < 8; nt++) {
                const float2 lo = __half22float2(*(const __half2*)&d16[mt][nt][0]);
                const float2 hi = __half22float2(*(const __half2*)&d16[mt][nt][1]);
                acc[mt][nt][0] += lo.x;
                acc[mt][nt][1] += lo.y;
                acc[mt][nt][2] += hi.x;
                acc[mt][nt][3] += hi.y;
            }
        }
    }

    // ---------------- epilogue: gate-scaled fp16 stores to g_slot -----------
    const int tq = lane & 3;          // column pair
    const int tr = lane >> 2;         // row within 8
#pragma unroll
    for (int mt = 0; mt < 2; mt++) {
#pragma unroll
        for (int hh = 0; hh < 2; hh++) {
            const int row = wm * 32 + mt * 16 + hh * 8 + tr;
            const int s = m0 + row;
            if (s < off1) {
                const float gv = gates[s];
                __half* dst = g_slot + (size_t)s * DOUT + n0 + wn * 64;
#pragma unroll
                for (int nt = 0; nt < 8; nt++) {
                    __half2 v = __floats2half2_rn(gv * acc[mt][nt][hh * 2 + 0],
                                                  gv * acc[mt][nt][hh * 2 + 1]);
                    *(__half2*)(dst + nt * 8 + tq * 2) = v;
                }
            }
        }
    }
}

// ---------------------------------------------------------------------------
// Combine: out[t] = slot[2t] + slot[2t+1]  (gate already folded in; fp16 in,
// fp32 math, fp32 out)
// ---------------------------------------------------------------------------
__global__ void combine_kernel(float* __restrict__ out) {
    const int i = blockIdx.x * blockDim.x + threadIdx.x;
    const int TOT = TOKENS * DOUT / 4;
    if (i < TOT) {
        const int t = i >> 8;            // 256 float4-groups per token row
        const int c = i & 255;           // group within row (4 elems)
        const __half2* sp = (const __half2*)g_slot;  // 512 half2 per slot row
        const size_t r0 = (size_t)(2 * t) * 512 + c * 2;
        const size_t r1 = r0 + 512;
        const float2 a0 = __half22float2(sp[r0]);
        const float2 a1 = __half22float2(sp[r0 + 1]);
        const float2 b0 = __half22float2(sp[r1]);
        const float2 b1 = __half22float2(sp[r1 + 1]);
        float4 o;
        o.x = a0.x + b0.x; o.y = a0.y + b0.y;
        o.z = a1.x + b1.x; o.w = a1.y + b1.y;
        ((float4*)out)[i] = o;
    }
}

// ---------------------------------------------------------------------------
// Launch. Inputs: 0 inputs, 1 weight, 2 gates, 3 k, 4 sorted_expert_idxs,
// 5 sorted_scattered_idxs, 6 expert_offsets
// ---------------------------------------------------------------------------
extern "C" void kernel_launch(void* const* d_in, const int* in_sizes, int n_in,
                              void* d_out, int out_size) {
    const float* x     = (const float*)d_in[0];
    const float* w     = (const float*)d_in[1];
    const float* gates = (const float*)d_in[2];
    const void*  scat  = d_in[5];
    const void*  offs  = d_in[6];
    float* out = (float*)d_out;

    cudaFuncSetAttribute(moe_mma_kernel,
                         cudaFuncAttributeMaxDynamicSharedMemorySize, SMEM_TOTAL);

    normalize_kernel<<<64, 512>>>(scat, offs);
    convert_kernel<<<2048, 256>>>(x, w);

    dim3 grid(DOUT / BN, NSLOTS / BM, NEXP);
    moe_mma_kernel<<<grid, 256, SMEM_TOTAL>>>(gates);

    combine_kernel<<<(TOKENS * DOUT / 4 + 255) / 256, 256>>>(out);
}

// round 16
// speedup vs baseline: 1.2967x; 1.2967x over previous
#include <cuda_runtime.h>
#include <cuda_fp16.h>
#include <cstdint>

// ---------------------------------------------------------------------------
// Problem constants
// ---------------------------------------------------------------------------
#define TOKENS  16384
#define DIN     1024
#define DOUT    1024
#define NEXP    8
#define TOPK    2
#define NSLOTS  (TOKENS * TOPK)   // 32768

// GEMM tiling (mma.sync m16n8k16 fp16, fp32 accum) — R13 proven config
#define BM 128
#define BN 128
#define BK 64
#define NK (DIN / BK)             // 16 k-chunks
#define NSTAGE 3

// smem: per stage 2 tiles (A, B), each 128 rows x 128B (64 fp16)
#define TILE_B   (128 * 128)      // 16384
#define ST_A     0
#define ST_B     (TILE_B)
#define STAGE_B  (2 * TILE_B)     // 32768
#define SMEM_TOTAL (NSTAGE * STAGE_B)   // 98304 -> 2 CTAs/SM

// ---------------------------------------------------------------------------
// Device scratch (no cudaMalloc allowed)
// ---------------------------------------------------------------------------
__device__ int g_row[NSLOTS];
__device__ int g_off[NEXP + 1];
__device__ __half g_xh[TOKENS * DIN];            // 32MB fp16 inputs
__device__ __half g_wh[NEXP * DOUT * DIN];       // 16MB fp16 weights
__device__ __half g_slot[(size_t)NSLOTS * DOUT]; // 64MB gate-scaled slot outputs (fp16)

// ---------------------------------------------------------------------------
// Helpers
// ---------------------------------------------------------------------------
__device__ __forceinline__ uint32_t smem_u32(const void* p) {
    uint32_t a;
    asm("{ .reg .u64 t; cvta.to.shared.u64 t, %1; cvt.u32.u64 %0, t; }" : "=r"(a) : "l"(p));
    return a;
}
__device__ __forceinline__ uint32_t swz128(uint32_t o) { return o ^ ((o >> 3) & 0x70); }

__device__ __forceinline__ void cpa16(uint32_t dst, const void* src) {
    asm volatile("cp.async.cg.shared.global [%0], [%1], 16;" :: "r"(dst), "l"(src) : "memory");
}
#define CPA_COMMIT() asm volatile("cp.async.commit_group;" ::: "memory")
#define CPA_WAIT(n)  asm volatile("cp.async.wait_group %0;" :: "n"(n) : "memory")

__device__ __forceinline__ void ldsm_x4(uint32_t* r, uint32_t addr) {
    asm volatile("ldmatrix.sync.aligned.m8n8.x4.shared.b16 {%0,%1,%2,%3}, [%4];"
                 : "=r"(r[0]), "=r"(r[1]), "=r"(r[2]), "=r"(r[3]) : "r"(addr));
}

__device__ __forceinline__ void mma_fp16(float* c, const uint32_t* a, const uint32_t* b) {
    asm volatile(
        "mma.sync.aligned.m16n8k16.row.col.f32.f16.f16.f32 "
        "{%0,%1,%2,%3}, {%4,%5,%6,%7}, {%8,%9}, {%0,%1,%2,%3};"
        : "+f"(c[0]), "+f"(c[1]), "+f"(c[2]), "+f"(c[3])
        : "r"(a[0]), "r"(a[1]), "r"(a[2]), "r"(a[3]), "r"(b[0]), "r"(b[1]));
}

// ---------------------------------------------------------------------------
// Index normalization (int32/int64 auto-detect; validated in R3)
// ---------------------------------------------------------------------------
__global__ void normalize_kernel(const void* __restrict__ scat,
                                 const void* __restrict__ offs) {
    const unsigned* ow = (const unsigned*)offs;
    const bool is64 = (ow[1] == 0u);
    int gid = blockIdx.x * blockDim.x + threadIdx.x;
    int stride = gridDim.x * blockDim.x;
    if (gid == 0) g_off[0] = 0;
    if (gid >= 1 && gid <= NEXP) {
        g_off[gid] = is64 ? (int)((const long long*)offs)[gid - 1]
                          : ((const int*)offs)[gid - 1];
    }
    for (int s = gid; s < NSLOTS; s += stride) {
        long long v = is64 ? ((const long long*)scat)[s]
                           : (long long)((const int*)scat)[s];
        g_row[s] = (int)(v / TOPK);
    }
}

// ---------------------------------------------------------------------------
// fp32 -> fp16 conversion for x and W
// ---------------------------------------------------------------------------
__global__ void convert_kernel(const float* __restrict__ x,
                               const float* __restrict__ w) {
    int gid = blockIdx.x * blockDim.x + threadIdx.x;
    int stride = gridDim.x * blockDim.x;
    const int NX4 = TOKENS * DIN / 4;
    const int NW4 = NEXP * DOUT * DIN / 4;
    const float4* x4 = (const float4*)x;
    const float4* w4 = (const float4*)w;
    __half2* xh = (__half2*)g_xh;
    __half2* wh = (__half2*)g_wh;
    for (int i = gid; i < NX4; i += stride) {
        float4 v = x4[i];
        xh[2 * i + 0] = __floats2half2_rn(v.x, v.y);
        xh[2 * i + 1] = __floats2half2_rn(v.z, v.w);
    }
    for (int i = gid; i < NW4; i += stride) {
        float4 v = w4[i];
        wh[2 * i + 0] = __floats2half2_rn(v.x, v.y);
        wh[2 * i + 1] = __floats2half2_rn(v.z, v.w);
    }
}

// ---------------------------------------------------------------------------
// mma.sync fp16 grouped GEMM (fp32 accumulate), 3-stage cp.async pipeline,
// 2 CTAs/SM. Proven R13 mainloop; fp16 gate-scaled epilogue (R15's win).
// grid: x = n-tile (8), y = m-tile within expert (256), z = expert (8)
// 256 threads = 8 warps in 4(m) x 2(n); warp tile 32x64.
// ---------------------------------------------------------------------------
__global__ __launch_bounds__(256, 2)
void moe_mma_kernel(const float* __restrict__ gates) {
    const int e    = blockIdx.z;
    const int off0 = g_off[e];
    const int off1 = g_off[e + 1];
    const int m0   = off0 + blockIdx.y * BM;
    if (m0 >= off1) return;
    const int n0   = blockIdx.x * BN;

    extern __shared__ char smem[];
    const uint32_t sb = smem_u32(smem);
    const int tid  = threadIdx.x;
    const int lane = tid & 31;
    const int wid  = tid >> 5;
    const int wm   = wid & 3;         // m-warp 0..3
    const int wn   = wid >> 2;        // n-warp 0..1

    // ---------------- loader setup: thread -> (row, half-row) --------------
    const int lr = tid >> 1;          // row 0..127 (both A and B tiles)
    const int lh = tid & 1;           // which half of the 128B row
    int sclamp = m0 + lr;
    if (sclamp >= off1) sclamp = off1 - 1;
    const int rowA = g_row[sclamp];
    const __half* pA = g_xh + (size_t)rowA * DIN;
    const __half* pB = g_wh + ((size_t)e << 20) + (size_t)(n0 + lr) * DIN;
    uint32_t so[4];                   // swizzled dst offsets within a tile
#pragma unroll
    for (int j = 0; j < 4; j++)
        so[j] = swz128((uint32_t)lr * 128 + (uint32_t)(lh * 4 + j) * 16);

    // accumulators: [mt][nt][4]
    float acc[2][8][4];
#pragma unroll
    for (int mt = 0; mt < 2; mt++)
#pragma unroll
        for (int nt = 0; nt < 8; nt++)
#pragma unroll
            for (int q = 0; q < 4; q++) acc[mt][nt][q] = 0.f;

    // ---------------- prefetch stages 0..NSTAGE-2 ----------------
#pragma unroll
    for (int ps = 0; ps < NSTAGE - 1; ps++) {
        const uint32_t base = sb + ps * STAGE_B;
        const int k0 = ps * BK;
#pragma unroll
        for (int j = 0; j < 4; j++) {
            const int eo = k0 + (lh * 4 + j) * 8;
            cpa16(base + ST_A + so[j], pA + eo);
            cpa16(base + ST_B + so[j], pB + eo);
        }
        CPA_COMMIT();
    }

    // ldmatrix address lane maps (validated R10/R13)
    const int a_r = lane & 15, a_c = lane >> 4;                        // A x4
    const int b_r = lane & 7, b_k = (lane >> 3) & 1, b_n = lane >> 4;  // B x4

    // ---------------- main loop ----------------
    for (int kc = 0; kc < NK; kc++) {
        CPA_WAIT(NSTAGE - 2);
        __syncthreads();

        // issue loads for chunk kc+NSTAGE-1
        const int nk = kc + NSTAGE - 1;
        if (nk < NK) {
            const uint32_t base = sb + (nk % NSTAGE) * STAGE_B;
            const int k0 = nk * BK;
#pragma unroll
            for (int j = 0; j < 4; j++) {
                const int eo = k0 + (lh * 4 + j) * 8;
                cpa16(base + ST_A + so[j], pA + eo);
                cpa16(base + ST_B + so[j], pB + eo);
            }
        }
        CPA_COMMIT();

        // compute on stage kc%NSTAGE
        const uint32_t base = sb + (kc % NSTAGE) * STAGE_B;
#pragma unroll
        for (int ks = 0; ks < 4; ks++) {
            uint32_t af[2][4];
#pragma unroll
            for (int mt = 0; mt < 2; mt++) {
                const uint32_t off =
                    swz128((uint32_t)(wm * 32 + mt * 16 + a_r) * 128 +
                           (uint32_t)(ks * 32 + a_c * 16));
                ldsm_x4(af[mt], base + ST_A + off);
            }
            uint32_t bf[4][4];
#pragma unroll
            for (int g = 0; g < 4; g++) {
                const uint32_t off =
                    swz128((uint32_t)(wn * 64 + g * 16 + b_n * 8 + b_r) * 128 +
                           (uint32_t)(ks * 32 + b_k * 16));
                ldsm_x4(bf[g], base + ST_B + off);
            }
#pragma unroll
            for (int mt = 0; mt < 2; mt++) {
#pragma unroll
                for (int g = 0; g < 4; g++) {
                    mma_fp16(acc[mt][2 * g],     af[mt], &bf[g][0]);
                    mma_fp16(acc[mt][2 * g + 1], af[mt], &bf[g][2]);
                }
            }
        }
    }

    // ---------------- epilogue: gate-scaled fp16 stores to g_slot -----------
    const int tq = lane & 3;          // column pair
    const int tr = lane >> 2;         // row within 8
#pragma unroll
    for (int mt = 0; mt < 2; mt++) {
#pragma unroll
        for (int hh = 0; hh < 2; hh++) {
            const int row = wm * 32 + mt * 16 + hh * 8 + tr;
            const int s = m0 + row;
            if (s < off1) {
                const float gv = gates[s];
                __half* dst = g_slot + (size_t)s * DOUT + n0 + wn * 64;
#pragma unroll
                for (int nt = 0; nt < 8; nt++) {
                    __half2 v = __floats2half2_rn(gv * acc[mt][nt][hh * 2 + 0],
                                                  gv * acc[mt][nt][hh * 2 + 1]);
                    *(__half2*)(dst + nt * 8 + tq * 2) = v;
                }
            }
        }
    }
}

// ---------------------------------------------------------------------------
// Combine: out[t] = slot[2t] + slot[2t+1]  (gate already folded in).
// 32B of output per thread: 2 x uint4 fp16 loads (MLP), 2 x float4 stores.
// ---------------------------------------------------------------------------
__global__ void combine_kernel(float* __restrict__ out) {
    const int i = blockIdx.x * blockDim.x + threadIdx.x;
    const int TOT = TOKENS * DOUT / 8;           // 8 outputs per thread
    if (i < TOT) {
        const int t = i >> 7;                    // 128 x 16B chunks per slot row
        const int c = i & 127;
        const uint4* sp = (const uint4*)g_slot;
        const uint4 A = sp[((size_t)(2 * t)) * 128 + c];      // 8 halves
        const uint4 B = sp[((size_t)(2 * t) + 1) * 128 + c];  // 8 halves
        const float2 a0 = __half22float2(*(const __half2*)&A.x);
        const float2 a1 = __half22float2(*(const __half2*)&A.y);
        const float2 a2 = __half22float2(*(const __half2*)&A.z);
        const float2 a3 = __half22float2(*(const __half2*)&A.w);
        const float2 b0 = __half22float2(*(const __half2*)&B.x);
        const float2 b1 = __half22float2(*(const __half2*)&B.y);
        const float2 b2 = __half22float2(*(const __half2*)&B.z);
        const float2 b3 = __half22float2(*(const __half2*)&B.w);
        float4 o0, o1;
        o0.x = a0.x + b0.x; o0.y = a0.y + b0.y;
        o0.z = a1.x + b1.x; o0.w = a1.y + b1.y;
        o1.x = a2.x + b2.x; o1.y = a2.y + b2.y;
        o1.z = a3.x + b3.x; o1.w = a3.y + b3.y;
        float4* op = (float4*)out + (size_t)i * 2;
        op[0] = o0;
        op[1] = o1;
    }
}

// ---------------------------------------------------------------------------
// Launch. Inputs: 0 inputs, 1 weight, 2 gates, 3 k, 4 sorted_expert_idxs,
// 5 sorted_scattered_idxs, 6 expert_offsets
// ---------------------------------------------------------------------------
extern "C" void kernel_launch(void* const* d_in, const int* in_sizes, int n_in,
                              void* d_out, int out_size) {
    const float* x     = (const float*)d_in[0];
    const float* w     = (const float*)d_in[1];
    const float* gates = (const float*)d_in[2];
    const void*  scat  = d_in[5];
    const void*  offs  = d_in[6];
    float* out = (float*)d_out;

    cudaFuncSetAttribute(moe_mma_kernel,
                         cudaFuncAttributeMaxDynamicSharedMemorySize, SMEM_TOTAL);

    normalize_kernel<<<64, 512>>>(scat, offs);
    convert_kernel<<<2048, 256>>>(x, w);

    dim3 grid(DOUT / BN, NSLOTS / BM, NEXP);
    moe_mma_kernel<<<grid, 256, SMEM_TOTAL>>>(gates);

    combine_kernel<<<(TOKENS * DOUT / 8 + 255) / 256, 256>>>(out);
}

// round 17
// speedup vs baseline: 1.3938x; 1.0749x over previous
#include <cuda_runtime.h>
#include <cuda_fp16.h>
#include <cstdint>

// ---------------------------------------------------------------------------
// Problem constants
// ---------------------------------------------------------------------------
#define TOKENS  16384
#define DIN     1024
#define DOUT    1024
#define NEXP    8
#define TOPK    2
#define NSLOTS  (TOKENS * TOPK)   // 32768

// GEMM tiling (mma.sync m16n8k16 fp16, fp32 accum) — R13 proven config
#define BM 128
#define BN 128
#define BK 64
#define NK (DIN / BK)             // 16 k-chunks
#define NSTAGE 3

// smem: per stage 2 tiles (A, B), each 128 rows x 128B (64 fp16)
#define TILE_B   (128 * 128)      // 16384
#define ST_A     0
#define ST_B     (TILE_B)
#define STAGE_B  (2 * TILE_B)     // 32768
#define SMEM_TOTAL (NSTAGE * STAGE_B)   // 98304 -> 2 CTAs/SM

// ---------------------------------------------------------------------------
// Device scratch (no cudaMalloc allowed)
// ---------------------------------------------------------------------------
__device__ int g_row[NSLOTS];
__device__ int g_off[NEXP + 1];
__device__ __half g_xh[TOKENS * DIN];            // 32MB fp16 inputs
__device__ __half g_wh[NEXP * DOUT * DIN];       // 16MB fp16 weights

// ---------------------------------------------------------------------------
// Helpers
// ---------------------------------------------------------------------------
__device__ __forceinline__ uint32_t smem_u32(const void* p) {
    uint32_t a;
    asm("{ .reg .u64 t; cvta.to.shared.u64 t, %1; cvt.u32.u64 %0, t; }" : "=r"(a) : "l"(p));
    return a;
}
__device__ __forceinline__ uint32_t swz128(uint32_t o) { return o ^ ((o >> 3) & 0x70); }

__device__ __forceinline__ void cpa16(uint32_t dst, const void* src) {
    asm volatile("cp.async.cg.shared.global [%0], [%1], 16;" :: "r"(dst), "l"(src) : "memory");
}
#define CPA_COMMIT() asm volatile("cp.async.commit_group;" ::: "memory")
#define CPA_WAIT(n)  asm volatile("cp.async.wait_group %0;" :: "n"(n) : "memory")

__device__ __forceinline__ void ldsm_x4(uint32_t* r, uint32_t addr) {
    asm volatile("ldmatrix.sync.aligned.m8n8.x4.shared.b16 {%0,%1,%2,%3}, [%4];"
                 : "=r"(r[0]), "=r"(r[1]), "=r"(r[2]), "=r"(r[3]) : "r"(addr));
}

__device__ __forceinline__ void mma_fp16(float* c, const uint32_t* a, const uint32_t* b) {
    asm volatile(
        "mma.sync.aligned.m16n8k16.row.col.f32.f16.f16.f32 "
        "{%0,%1,%2,%3}, {%4,%5,%6,%7}, {%8,%9}, {%0,%1,%2,%3};"
        : "+f"(c[0]), "+f"(c[1]), "+f"(c[2]), "+f"(c[3])
        : "r"(a[0]), "r"(a[1]), "r"(a[2]), "r"(a[3]), "r"(b[0]), "r"(b[1]));
}

// ---------------------------------------------------------------------------
// Normalization: g_row/g_off tables (int32/int64 auto-detect, validated R3)
// + zero the <=7 boundary-split token rows (odd expert offsets), which the
// mma epilogue fills via two commutative fp32 atomicAdds.
// ---------------------------------------------------------------------------
__global__ void normalize_kernel(const void* __restrict__ scat,
                                 const void* __restrict__ offs,
                                 float* __restrict__ out) {
    const unsigned* ow = (const unsigned*)offs;
    const bool is64 = (ow[1] == 0u);
    int gid = blockIdx.x * blockDim.x + threadIdx.x;
    int stride = gridDim.x * blockDim.x;
    if (gid == 0) g_off[0] = 0;
    if (gid >= 1 && gid <= NEXP) {
        g_off[gid] = is64 ? (int)((const long long*)offs)[gid - 1]
                          : ((const int*)offs)[gid - 1];
    }
    // zero boundary-split token rows: interior boundaries offs[0..NEXP-2]
    if (gid < (NEXP - 1) * DOUT) {
        const int b = gid / DOUT;
        const int c = gid % DOUT;
        const long long off = is64 ? ((const long long*)offs)[b]
                                   : (long long)((const int*)offs)[b];
        if (off & 1) out[(size_t)((off - 1) >> 1) * DOUT + c] = 0.f;
    }
    for (int s = gid; s < NSLOTS; s += stride) {
        long long v = is64 ? ((const long long*)scat)[s]
                           : (long long)((const int*)scat)[s];
        g_row[s] = (int)(v / TOPK);
    }
}

// ---------------------------------------------------------------------------
// fp32 -> fp16 conversion for x and W
// ---------------------------------------------------------------------------
__global__ void convert_kernel(const float* __restrict__ x,
                               const float* __restrict__ w) {
    int gid = blockIdx.x * blockDim.x + threadIdx.x;
    int stride = gridDim.x * blockDim.x;
    const int NX4 = TOKENS * DIN / 4;
    const int NW4 = NEXP * DOUT * DIN / 4;
    const float4* x4 = (const float4*)x;
    const float4* w4 = (const float4*)w;
    __half2* xh = (__half2*)g_xh;
    __half2* wh = (__half2*)g_wh;
    for (int i = gid; i < NX4; i += stride) {
        float4 v = x4[i];
        xh[2 * i + 0] = __floats2half2_rn(v.x, v.y);
        xh[2 * i + 1] = __floats2half2_rn(v.z, v.w);
    }
    for (int i = gid; i < NW4; i += stride) {
        float4 v = w4[i];
        wh[2 * i + 0] = __floats2half2_rn(v.x, v.y);
        wh[2 * i + 1] = __floats2half2_rn(v.z, v.w);
    }
}

// ---------------------------------------------------------------------------
// mma.sync fp16 grouped GEMM (fp32 accumulate), 3-stage cp.async pipeline,
// 2 CTAs/SM. Fused gate-combine epilogue:
//   tiles are EVEN-slot aligned (base = off0 & ~1), so token pairs
//   {2t, 2t+1} are adjacent rows in one tile. Each lane gate-scales its rows,
//   shfl_xor(4) fetches the partner row, even rows write final fp32 output.
//   Pairs split across an expert boundary (odd offset) use atomicAdd (2
//   commutative adds -> deterministic; rows pre-zeroed by normalize_kernel).
// grid: x = n-tile (8), y = m-tile (257), z = expert (8)
// 256 threads = 8 warps in 4(m) x 2(n); warp tile 32x64.
// ---------------------------------------------------------------------------
__global__ __launch_bounds__(256, 2)
void moe_mma_kernel(const float* __restrict__ gates, float* __restrict__ out) {
    const int e    = blockIdx.z;
    const int off0 = g_off[e];
    const int off1 = g_off[e + 1];
    const int mbase = (off0 & ~1) + blockIdx.y * BM;   // even-aligned tile base
    if (mbase >= off1) return;
    const int n0   = blockIdx.x * BN;

    extern __shared__ char smem[];
    const uint32_t sb = smem_u32(smem);
    const int tid  = threadIdx.x;
    const int lane = tid & 31;
    const int wid  = tid >> 5;
    const int wm   = wid & 3;         // m-warp 0..3
    const int wn   = wid >> 2;        // n-warp 0..1

    // ---------------- loader setup: thread -> (row, half-row) --------------
    const int lr = tid >> 1;          // row 0..127 (both A and B tiles)
    const int lh = tid & 1;           // which half of the 128B row
    int sclamp = mbase + lr;
    if (sclamp < off0) sclamp = off0;
    if (sclamp >= off1) sclamp = off1 - 1;
    const int rowA = g_row[sclamp];
    const __half* pA = g_xh + (size_t)rowA * DIN;
    const __half* pB = g_wh + ((size_t)e << 20) + (size_t)(n0 + lr) * DIN;
    uint32_t so[4];                   // swizzled dst offsets within a tile
#pragma unroll
    for (int j = 0; j < 4; j++)
        so[j] = swz128((uint32_t)lr * 128 + (uint32_t)(lh * 4 + j) * 16);

    // accumulators: [mt][nt][4]
    float acc[2][8][4];
#pragma unroll
    for (int mt = 0; mt < 2; mt++)
#pragma unroll
        for (int nt = 0; nt < 8; nt++)
#pragma unroll
            for (int q = 0; q < 4; q++) acc[mt][nt][q] = 0.f;

    // ---------------- prefetch stages 0..NSTAGE-2 ----------------
#pragma unroll
    for (int ps = 0; ps < NSTAGE - 1; ps++) {
        const uint32_t base = sb + ps * STAGE_B;
        const int k0 = ps * BK;
#pragma unroll
        for (int j = 0; j < 4; j++) {
            const int eo = k0 + (lh * 4 + j) * 8;
            cpa16(base + ST_A + so[j], pA + eo);
            cpa16(base + ST_B + so[j], pB + eo);
        }
        CPA_COMMIT();
    }

    // ldmatrix address lane maps (validated R10/R13)
    const int a_r = lane & 15, a_c = lane >> 4;                        // A x4
    const int b_r = lane & 7, b_k = (lane >> 3) & 1, b_n = lane >> 4;  // B x4

    // ---------------- main loop ----------------
    for (int kc = 0; kc < NK; kc++) {
        CPA_WAIT(NSTAGE - 2);
        __syncthreads();

        // issue loads for chunk kc+NSTAGE-1
        const int nk = kc + NSTAGE - 1;
        if (nk < NK) {
            const uint32_t base = sb + (nk % NSTAGE) * STAGE_B;
            const int k0 = nk * BK;
#pragma unroll
            for (int j = 0; j < 4; j++) {
                const int eo = k0 + (lh * 4 + j) * 8;
                cpa16(base + ST_A + so[j], pA + eo);
                cpa16(base + ST_B + so[j], pB + eo);
            }
        }
        CPA_COMMIT();

        // compute on stage kc%NSTAGE
        const uint32_t base = sb + (kc % NSTAGE) * STAGE_B;
#pragma unroll
        for (int ks = 0; ks < 4; ks++) {
            uint32_t af[2][4];
#pragma unroll
            for (int mt = 0; mt < 2; mt++) {
                const uint32_t off =
                    swz128((uint32_t)(wm * 32 + mt * 16 + a_r) * 128 +
                           (uint32_t)(ks * 32 + a_c * 16));
                ldsm_x4(af[mt], base + ST_A + off);
            }
            uint32_t bf[4][4];
#pragma unroll
            for (int g = 0; g < 4; g++) {
                const uint32_t off =
                    swz128((uint32_t)(wn * 64 + g * 16 + b_n * 8 + b_r) * 128 +
                           (uint32_t)(ks * 32 + b_k * 16));
                ldsm_x4(bf[g], base + ST_B + off);
            }
#pragma unroll
            for (int mt = 0; mt < 2; mt++) {
#pragma unroll
                for (int g = 0; g < 4; g++) {
                    mma_fp16(acc[mt][2 * g],     af[mt], &bf[g][0]);
                    mma_fp16(acc[mt][2 * g + 1], af[mt], &bf[g][2]);
                }
            }
        }
    }

    // ---------------- fused gate-combine epilogue ----------------
    // Fragment row = wm*32 + mt*16 + hh*8 + tr; partner row differs in bit 0
    // of tr -> partner lane = lane ^ 4. Even-tr lanes own token (s>>1).
    const int tq = lane & 3;          // column pair
    const int tr = lane >> 2;         // row within 8
#pragma unroll
    for (int mt = 0; mt < 2; mt++) {
#pragma unroll
        for (int hh = 0; hh < 2; hh++) {
            const int row = wm * 32 + mt * 16 + hh * 8 + tr;
            const int s = mbase + row;
            const bool valid = (s >= off0) && (s < off1);
            const float gv = valid ? gates[s] : 0.f;

            float v[16];
#pragma unroll
            for (int nt = 0; nt < 8; nt++) {
                v[2 * nt + 0] = gv * acc[mt][nt][hh * 2 + 0];
                v[2 * nt + 1] = gv * acc[mt][nt][hh * 2 + 1];
            }
            float p[16];
#pragma unroll
            for (int i = 0; i < 16; i++)
                p[i] = __shfl_xor_sync(0xffffffffu, v[i], 4);
            const int pvalid = __shfl_xor_sync(0xffffffffu, (int)valid, 4);

            if ((tr & 1) == 0 && (valid || pvalid)) {
                float* dst = out + (size_t)(s >> 1) * DOUT + n0 + wn * 64;
                if (valid && pvalid) {
                    // whole pair in-tile: plain final store
#pragma unroll
                    for (int nt = 0; nt < 8; nt++) {
                        float2 o;
                        o.x = v[2 * nt + 0] + p[2 * nt + 0];
                        o.y = v[2 * nt + 1] + p[2 * nt + 1];
                        *(float2*)(dst + nt * 8 + tq * 2) = o;
                    }
                } else {
                    // boundary-split pair: both owning CTAs atomicAdd
#pragma unroll
                    for (int nt = 0; nt < 8; nt++) {
                        atomicAdd(dst + nt * 8 + tq * 2 + 0, v[2 * nt + 0] + p[2 * nt + 0]);
                        atomicAdd(dst + nt * 8 + tq * 2 + 1, v[2 * nt + 1] + p[2 * nt + 1]);
                    }
                }
            }
        }
    }
}

// ---------------------------------------------------------------------------
// Launch. Inputs: 0 inputs, 1 weight, 2 gates, 3 k, 4 sorted_expert_idxs,
// 5 sorted_scattered_idxs, 6 expert_offsets
// ---------------------------------------------------------------------------
extern "C" void kernel_launch(void* const* d_in, const int* in_sizes, int n_in,
                              void* d_out, int out_size) {
    const float* x     = (const float*)d_in[0];
    const float* w     = (const float*)d_in[1];
    const float* gates = (const float*)d_in[2];
    const void*  scat  = d_in[5];
    const void*  offs  = d_in[6];
    float* out = (float*)d_out;

    cudaFuncSetAttribute(moe_mma_kernel,
                         cudaFuncAttributeMaxDynamicSharedMemorySize, SMEM_TOTAL);

    normalize_kernel<<<64, 512>>>(scat, offs, out);
    convert_kernel<<<2048, 256>>>(x, w);

    // y = NSLOTS/BM + 1: even-aligned tile bases can shift ranges by one tile
    dim3 grid(DOUT / BN, NSLOTS / BM + 1, NEXP);
    moe_mma_kernel<<<grid, 256, SMEM_TOTAL>>>(gates, out);
}